// round 14
// baseline (speedup 1.0000x reference)
#include <cuda_runtime.h>
#include <cuda_bf16.h>
#include <cstdint>

// SpatialBlock: x[16,256,128,128] fp32
//   max_c(x), mean_c(x) -> conv7x7 (2->1, SAME zero pad) + bias -> hsigmoid -> x * gate
//
// R14: 2-stream forked capture. Chunked L2 reuse works (70%+ hits, R12/R13)
//      but phase serialization wasted it. Now reduce(k) on the capture stream,
//      gate(k) on stream2 after event(reduce(k)); reduce(k+1) overlaps gate(k),
//      keeping DRAM read + write paths busy simultaneously. CHUNK=2 batches
//      (33.5 MB) so the overlapped L2 working set (67 MB) fits in 126 MB.
//      Streams/events created once on the first (pre-capture) call.

#define Bn 16
#define Cn 256
#define Hn 128
#define Wn 128
#define HWn (Hn * Wn)
#define PLANE4 (HWn / 4)      // 4096 float4 per plane

#define CHUNK 2               // batches per chunk
#define NCHUNK (Bn / CHUNK)   // 8 chunks

__device__ float g_max[Bn * HWn];
__device__ float g_avg[Bn * HWn];

#define RPX 64                 // float4 pixels per reduce block (1 KB per channel)
#define CPS 8                  // channels per pipeline stage
#define NSTG 3                 // ring stages (24 KB)
#define NSTEPS (Cn / CPS)      // 32 steps

__device__ __forceinline__ uint32_t smem_u32(const void* p) {
    uint32_t a;
    asm("{ .reg .u64 t; cvta.to.shared.u64 t, %1; cvt.u32.u64 %0, t; }"
        : "=r"(a) : "l"(p));
    return a;
}

__global__ void __launch_bounds__(160)
reduce_kernel(const float* __restrict__ x, int batch0) {
    __shared__ __align__(16) float4 buf[NSTG][CPS][RPX];   // 24 KB
    __shared__ __align__(16) float4 smx[2][RPX];
    __shared__ __align__(16) float4 ssm[2][RPX];
    __shared__ uint64_t mb_full[NSTG];
    __shared__ uint64_t mb_empty[NSTG];

    int tid = threadIdx.x;
    int b   = batch0 + blockIdx.x / (PLANE4 / RPX);  // 64 blocks per plane
    int p0  = (blockIdx.x % (PLANE4 / RPX)) * RPX;   // first float4 pixel

    if (tid == 0) {
        for (int s = 0; s < NSTG; s++) {
            asm volatile("mbarrier.init.shared.b64 [%0], %1;"
                         :: "r"(smem_u32(&mb_full[s])), "r"(1) : "memory");
            asm volatile("mbarrier.init.shared.b64 [%0], %1;"
                         :: "r"(smem_u32(&mb_empty[s])), "r"(128) : "memory");
        }
        asm volatile("fence.proxy.async.shared::cta;" ::: "memory");
    }
    __syncthreads();

    if (tid >= 128) {
        // ---------- producer warp (one elected thread) ----------
        if (tid == 128) {
            const float4* src0 = reinterpret_cast<const float4*>(x) +
                                 (size_t)b * Cn * PLANE4 + p0;
            int slot = 0, ph = 1;          // phase trick: first empty-wait passes
            for (int s = 0; s < NSTEPS; s++) {
                uint32_t e = smem_u32(&mb_empty[slot]);
                asm volatile(
                    "{\n\t.reg .pred P;\n\t"
                    "PW%=:\n\t"
                    "mbarrier.try_wait.parity.relaxed.cta.shared::cta.b64 P, [%0], %1;\n\t"
                    "@!P bra PW%=;\n\t}"
                    :: "r"(e), "r"(ph) : "memory");

                uint32_t f = smem_u32(&mb_full[slot]);
                asm volatile("mbarrier.arrive.expect_tx.shared.b64 _, [%0], %1;"
                             :: "r"(f), "r"(CPS * RPX * 16) : "memory");
#pragma unroll
                for (int c = 0; c < CPS; c++) {
                    const float4* src = src0 + (size_t)(s * CPS + c) * PLANE4;
                    uint32_t d = smem_u32(&buf[slot][c][0]);
                    asm volatile(
                        "cp.async.bulk.shared::cta.global.mbarrier::complete_tx::bytes "
                        "[%0], [%1], %2, [%3];"
                        :: "r"(d), "l"(src), "r"(RPX * 16), "r"(f) : "memory");
                }
                if (++slot == NSTG) { slot = 0; ph ^= 1; }
            }
        }
    } else {
        // ---------- 128 consumers: (px, channel-parity h) ----------
        int px = tid & 63;
        int h  = tid >> 6;

        float4 mx = make_float4(-3.402823466e38f, -3.402823466e38f,
                                -3.402823466e38f, -3.402823466e38f);
        float4 sm = make_float4(0.f, 0.f, 0.f, 0.f);

        int slot = 0, ph = 0;
        for (int s = 0; s < NSTEPS; s++) {
            uint32_t f = smem_u32(&mb_full[slot]);
            asm volatile(
                "{\n\t.reg .pred P;\n\t"
                "CW%=:\n\t"
                "mbarrier.try_wait.parity.acquire.cta.shared::cta.b64 P, [%0], %1;\n\t"
                "@!P bra CW%=;\n\t}"
                :: "r"(f), "r"(ph) : "memory");

#pragma unroll
            for (int cl = 0; cl < CPS / 2; cl++) {
                float4 u = buf[slot][2 * cl + h][px];
                mx.x = fmaxf(mx.x, u.x); mx.y = fmaxf(mx.y, u.y);
                mx.z = fmaxf(mx.z, u.z); mx.w = fmaxf(mx.w, u.w);
                sm.x += u.x; sm.y += u.y; sm.z += u.z; sm.w += u.w;
            }

            asm volatile("mbarrier.arrive.shared.b64 _, [%0];"
                         :: "r"(smem_u32(&mb_empty[slot])) : "memory");
            if (++slot == NSTG) { slot = 0; ph ^= 1; }
        }
        smx[h][px] = mx;
        ssm[h][px] = sm;
    }
    __syncthreads();

    if (tid < RPX) {
        int px = tid;
        float4 m0 = smx[0][px], m1 = smx[1][px];
        float4 s0 = ssm[0][px], s1 = ssm[1][px];
        float4 mo, so;
        mo.x = fmaxf(m0.x, m1.x); mo.y = fmaxf(m0.y, m1.y);
        mo.z = fmaxf(m0.z, m1.z); mo.w = fmaxf(m0.w, m1.w);
        const float inv = 1.0f / (float)Cn;
        so.x = (s0.x + s1.x) * inv; so.y = (s0.y + s1.y) * inv;
        so.z = (s0.z + s1.z) * inv; so.w = (s0.w + s1.w) * inv;

        reinterpret_cast<float4*>(g_max)[(size_t)b * PLANE4 + p0 + px] = mo;
        reinterpret_cast<float4*>(g_avg)[(size_t)b * PLANE4 + p0 + px] = so;
    }
}

#define TW 32   // tile width  (pixels) -- 128B rows, full-line warp requests
#define TH 4    // tile height (pixels)

__global__ void __launch_bounds__(256)
gate_mul_kernel(const float* __restrict__ x,
                const float* __restrict__ cw,   // [1,2,7,7] = 98 floats
                const float* __restrict__ cb,   // [1]
                float* __restrict__ out, int batch0) {
    __shared__ float sw[98];
    __shared__ float sbias;
    __shared__ __align__(16) float smax[TH + 6][TW + 6];
    __shared__ __align__(16) float savg[TH + 6][TW + 6];
    __shared__ __align__(16) float sgate[TH][TW];

    int tid = threadIdx.x;                        // 0..255
    if (tid < 98) sw[tid] = cw[tid];
    if (tid == 98) sbias = cb[0];

    int b  = batch0 + blockIdx.z;
    int h0 = blockIdx.y * TH;
    int w0 = blockIdx.x * TW;

    const float* bmax = g_max + b * HWn;
    const float* bavg = g_avg + b * HWn;

    // Cooperative halo load (zero padding == conv SAME zero-pad). 10x38=380.
    for (int i = tid; i < (TH + 6) * (TW + 6); i += 256) {
        int r  = i / (TW + 6);
        int cc = i - r * (TW + 6);
        int hh = h0 + r - 3;
        int ww = w0 + cc - 3;
        float vm = 0.0f, va = 0.0f;
        if ((unsigned)hh < (unsigned)Hn && (unsigned)ww < (unsigned)Wn) {
            int gi = hh * Wn + ww;
            vm = bmax[gi];
            va = bavg[gi];
        }
        smax[r][cc] = vm;
        savg[r][cc] = va;
    }
    __syncthreads();

    // Conv + hsigmoid: threads 0..127 compute one pixel each of the 32x4 tile
    if (tid < TH * TW) {
        int r  = tid >> 5;         // 0..3
        int cp = tid & 31;         // 0..31
        float a0 = sbias;
#pragma unroll
        for (int ky = 0; ky < 7; ky++) {
#pragma unroll
            for (int kx = 0; kx < 7; kx++) {
                a0 += sw[ky * 7 + kx]      * smax[r + ky][cp + kx]
                    + sw[49 + ky * 7 + kx] * savg[r + ky][cp + kx];
            }
        }
        sgate[r][cp] = __saturatef((a0 + 3.0f) * (1.0f / 6.0f));
    }
    __syncthreads();

    // Broadcast multiply: thread = (channel-eighth, px4). 32 px4 in tile,
    // 8 eighths x 32 channels. Warp = 4 rows x 8 float4 = 128B/row.
    int px4 = tid & 31;            // 0..31
    int cg  = tid >> 5;            // 0..7
    int rr  = px4 >> 3;            // tile row 0..3
    int cc4 = px4 & 7;             // float4 col 0..7

    float4 g = *reinterpret_cast<const float4*>(&sgate[rr][cc4 * 4]);

    const size_t plane4 = HWn / 4;
    int prow4 = ((h0 + rr) * Wn + w0 + cc4 * 4) >> 2;
    const float4* xin = reinterpret_cast<const float4*>(x) +
                        (size_t)b * Cn * plane4 + (size_t)cg * 32 * plane4 + prow4;
    float4* xout = reinterpret_cast<float4*>(out) +
                   (size_t)b * Cn * plane4 + (size_t)cg * 32 * plane4 + prow4;

#pragma unroll 8
    for (int c = 0; c < 32; c++) {
        float4 v = __ldcs(xin + (size_t)c * plane4);
        v.x *= g.x; v.y *= g.y; v.z *= g.z; v.w *= g.w;
        __stcs(xout + (size_t)c * plane4, v);
    }
}

extern "C" void kernel_launch(void* const* d_in, const int* in_sizes, int n_in,
                              void* d_out, int out_size) {
    const float* x  = (const float*)d_in[0];
    const float* cw = (const float*)d_in[1];
    const float* cb = (const float*)d_in[2];
    float* out = (float*)d_out;

    // One-time host-side resource creation (streams/events are host objects,
    // no device memory). First call is the correctness run (pre-capture), so
    // creation never happens inside graph capture. Every call then performs
    // the identical launch sequence.
    static cudaStream_t s2 = nullptr;
    static cudaEvent_t evR[NCHUNK];
    static cudaEvent_t evJoin = nullptr;
    if (s2 == nullptr) {
        cudaStreamCreateWithFlags(&s2, cudaStreamNonBlocking);
        for (int k = 0; k < NCHUNK; k++)
            cudaEventCreateWithFlags(&evR[k], cudaEventDisableTiming);
        cudaEventCreateWithFlags(&evJoin, cudaEventDisableTiming);
    }

    for (int k = 0; k < NCHUNK; k++) {
        int b0 = k * CHUNK;
        // reduce chunk on the main (capture) stream: 128 blocks x 160 thr
        reduce_kernel<<<CHUNK * (PLANE4 / RPX), 160>>>(x, b0);
        cudaEventRecord(evR[k], 0);
        // gate chunk on stream2, ordered after reduce(k) only: overlaps
        // reduce(k+1). grid (4, 32, 2) = 256 blocks x 256 thr
        cudaStreamWaitEvent(s2, evR[k], 0);
        gate_mul_kernel<<<dim3(Wn / TW, Hn / TH, CHUNK), 256, 0, s2>>>(
            x, cw, cb, out, b0);
    }
    // Join stream2 back into the main stream so the graph's output node
    // depends on all gate chunks.
    cudaEventRecord(evJoin, s2);
    cudaStreamWaitEvent(0, evJoin, 0);
}

// round 16
// speedup vs baseline: 1.5948x; 1.5948x over previous
#include <cuda_runtime.h>
#include <cuda_bf16.h>
#include <cstdint>

// SpatialBlock: x[16,256,128,128] fp32
//   max_c(x), mean_c(x) -> conv7x7 (2->1, SAME zero pad) + bias -> hsigmoid -> x * gate
//
// R15: back to the R10 two-launch layout (best: 135.2us). Chunked L2 reuse
//      abandoned: 3 rounds showed launch serialization + small grids cost more
//      than the DRAM savings. New: reduce reads via BOTH hardware paths
//      concurrently -- channels 0..127 through the TMA bulk pipeline (path
//      ceiling 5.47 TB/s), channels 128..255 through direct LDG in the
//      consumers (path ceiling 5.2 TB/s), interleaved 4+4 per step so both
//      paths stay busy. Sum capped only by DRAM (~6.2 TB/s measured).
//      Gate_mul identical to R5/R10 (its ceiling).

#define Bn 16
#define Cn 256
#define Hn 128
#define Wn 128
#define HWn (Hn * Wn)
#define PLANE4 (HWn / 4)      // 4096 float4 per plane

__device__ float g_max[Bn * HWn];
__device__ float g_avg[Bn * HWn];

#define RPX 128                // float4 pixels per block (2 KB per channel)
#define CPS 8                  // channels per pipeline stage
#define NSTG 2                 // ring stages (32 KB buf)
#define NSTEPS 16              // TMA covers channels 0..127 (16 x 8)

__device__ __forceinline__ uint32_t smem_u32(const void* p) {
    uint32_t a;
    asm("{ .reg .u64 t; cvta.to.shared.u64 t, %1; cvt.u32.u64 %0, t; }"
        : "=r"(a) : "l"(p));
    return a;
}

__global__ void __launch_bounds__(288)
reduce_kernel(const float* __restrict__ x) {
    __shared__ __align__(16) float4 buf[NSTG][CPS][RPX];   // 32 KB
    __shared__ __align__(16) float4 smx[2][RPX];           // 4 KB
    __shared__ __align__(16) float4 ssm[2][RPX];           // 4 KB
    __shared__ uint64_t mb_full[NSTG];
    __shared__ uint64_t mb_empty[NSTG];

    int tid = threadIdx.x;
    int b   = blockIdx.x / (PLANE4 / RPX);           // 32 blocks per plane
    int p0  = (blockIdx.x % (PLANE4 / RPX)) * RPX;   // first float4 pixel

    if (tid == 0) {
        for (int s = 0; s < NSTG; s++) {
            asm volatile("mbarrier.init.shared.b64 [%0], %1;"
                         :: "r"(smem_u32(&mb_full[s])), "r"(1) : "memory");
            asm volatile("mbarrier.init.shared.b64 [%0], %1;"
                         :: "r"(smem_u32(&mb_empty[s])), "r"(256) : "memory");
        }
        asm volatile("fence.proxy.async.shared::cta;" ::: "memory");
    }
    __syncthreads();

    if (tid >= 256) {
        // ---------- producer warp: TMA path, channels 0..127 ----------
        if (tid == 256) {
            const float4* src0 = reinterpret_cast<const float4*>(x) +
                                 (size_t)b * Cn * PLANE4 + p0;
            int slot = 0, ph = 1;          // phase trick: first empty-wait passes
            for (int s = 0; s < NSTEPS; s++) {
                uint32_t e = smem_u32(&mb_empty[slot]);
                asm volatile(
                    "{\n\t.reg .pred P;\n\t"
                    "PW%=:\n\t"
                    "mbarrier.try_wait.parity.relaxed.cta.shared::cta.b64 P, [%0], %1;\n\t"
                    "@!P bra PW%=;\n\t}"
                    :: "r"(e), "r"(ph) : "memory");

                uint32_t f = smem_u32(&mb_full[slot]);
                asm volatile("mbarrier.arrive.expect_tx.shared.b64 _, [%0], %1;"
                             :: "r"(f), "r"(CPS * RPX * 16) : "memory");
#pragma unroll
                for (int c = 0; c < CPS; c++) {
                    const float4* src = src0 + (size_t)(s * CPS + c) * PLANE4;
                    uint32_t d = smem_u32(&buf[slot][c][0]);
                    asm volatile(
                        "cp.async.bulk.shared::cta.global.mbarrier::complete_tx::bytes "
                        "[%0], [%1], %2, [%3];"
                        :: "r"(d), "l"(src), "r"(RPX * 16), "r"(f) : "memory");
                }
                if (++slot == NSTG) { slot = 0; ph ^= 1; }
            }
        }
    } else {
        // ---------- 256 consumers: smem (ch 0..127) + direct LDG (ch 128..255)
        int px = tid & 127;
        int h  = tid >> 7;

        float4 mx = make_float4(-3.402823466e38f, -3.402823466e38f,
                                -3.402823466e38f, -3.402823466e38f);
        float4 sm = make_float4(0.f, 0.f, 0.f, 0.f);

        // Direct-LDG base: this thread's pixel, channel 128 + parity h
        const float4* dsrc = reinterpret_cast<const float4*>(x) +
                             (size_t)b * Cn * PLANE4 +
                             (size_t)(128 + h) * PLANE4 + p0 + px;

        int slot = 0, ph = 0;
        for (int s = 0; s < NSTEPS; s++) {
            uint32_t f = smem_u32(&mb_full[slot]);
            asm volatile(
                "{\n\t.reg .pred P;\n\t"
                "CW%=:\n\t"
                "mbarrier.try_wait.parity.acquire.cta.shared::cta.b64 P, [%0], %1;\n\t"
                "@!P bra CW%=;\n\t}"
                :: "r"(f), "r"(ph) : "memory");

            // 4 smem channels (parity h of this stage's 8)
#pragma unroll
            for (int cl = 0; cl < CPS / 2; cl++) {
                float4 u = buf[slot][2 * cl + h][px];
                mx.x = fmaxf(mx.x, u.x); mx.y = fmaxf(mx.y, u.y);
                mx.z = fmaxf(mx.z, u.z); mx.w = fmaxf(mx.w, u.w);
                sm.x += u.x; sm.y += u.y; sm.z += u.z; sm.w += u.w;
            }

            asm volatile("mbarrier.arrive.shared.b64 _, [%0];"
                         :: "r"(smem_u32(&mb_empty[slot])) : "memory");
            if (++slot == NSTG) { slot = 0; ph ^= 1; }

            // 4 direct channels on the LDG path: 128 + s*8 + 2*cl + h
#pragma unroll
            for (int cl = 0; cl < 4; cl++) {
                float4 u = __ldcs(dsrc + (size_t)(s * 8 + 2 * cl) * PLANE4);
                mx.x = fmaxf(mx.x, u.x); mx.y = fmaxf(mx.y, u.y);
                mx.z = fmaxf(mx.z, u.z); mx.w = fmaxf(mx.w, u.w);
                sm.x += u.x; sm.y += u.y; sm.z += u.z; sm.w += u.w;
            }
        }
        smx[h][px] = mx;
        ssm[h][px] = sm;
    }
    __syncthreads();

    if (tid < RPX) {
        int px = tid;
        float4 m0 = smx[0][px], m1 = smx[1][px];
        float4 s0 = ssm[0][px], s1 = ssm[1][px];
        float4 mo, so;
        mo.x = fmaxf(m0.x, m1.x); mo.y = fmaxf(m0.y, m1.y);
        mo.z = fmaxf(m0.z, m1.z); mo.w = fmaxf(m0.w, m1.w);
        const float inv = 1.0f / (float)Cn;
        so.x = (s0.x + s1.x) * inv; so.y = (s0.y + s1.y) * inv;
        so.z = (s0.z + s1.z) * inv; so.w = (s0.w + s1.w) * inv;

        reinterpret_cast<float4*>(g_max)[(size_t)b * PLANE4 + p0 + px] = mo;
        reinterpret_cast<float4*>(g_avg)[(size_t)b * PLANE4 + p0 + px] = so;
    }
}

#define TW 32   // tile width  (pixels) -- 128B rows, full-line warp requests
#define TH 8    // tile height (pixels)

__global__ void __launch_bounds__(256)
gate_mul_kernel(const float* __restrict__ x,
                const float* __restrict__ cw,   // [1,2,7,7] = 98 floats
                const float* __restrict__ cb,   // [1]
                float* __restrict__ out) {
    __shared__ float sw[98];
    __shared__ float sbias;
    __shared__ __align__(16) float smax[TH + 6][TW + 6];
    __shared__ __align__(16) float savg[TH + 6][TW + 6];
    __shared__ __align__(16) float sgate[TH][TW];

    int tid = threadIdx.x;                        // 0..255
    if (tid < 98) sw[tid] = cw[tid];
    if (tid == 98) sbias = cb[0];

    int b  = blockIdx.z;
    int h0 = blockIdx.y * TH;
    int w0 = blockIdx.x * TW;

    const float* bmax = g_max + b * HWn;
    const float* bavg = g_avg + b * HWn;

    // Cooperative halo load (zero padding == conv SAME zero-pad). 14x38=532.
    for (int i = tid; i < (TH + 6) * (TW + 6); i += 256) {
        int r  = i / (TW + 6);
        int cc = i - r * (TW + 6);
        int hh = h0 + r - 3;
        int ww = w0 + cc - 3;
        float vm = 0.0f, va = 0.0f;
        if ((unsigned)hh < (unsigned)Hn && (unsigned)ww < (unsigned)Wn) {
            int gi = hh * Wn + ww;
            vm = bmax[gi];
            va = bavg[gi];
        }
        smax[r][cc] = vm;
        savg[r][cc] = va;
    }
    __syncthreads();

    // Conv + hsigmoid: 256 threads, one pixel each of the 32x8 tile
    {
        int r  = tid >> 5;         // 0..7
        int cp = tid & 31;         // 0..31
        float a0 = sbias;
#pragma unroll
        for (int ky = 0; ky < 7; ky++) {
#pragma unroll
            for (int kx = 0; kx < 7; kx++) {
                a0 += sw[ky * 7 + kx]      * smax[r + ky][cp + kx]
                    + sw[49 + ky * 7 + kx] * savg[r + ky][cp + kx];
            }
        }
        sgate[r][cp] = __saturatef((a0 + 3.0f) * (1.0f / 6.0f));
    }
    __syncthreads();

    // Broadcast multiply: thread = (channel-quarter, px4). 64 px4 in tile,
    // 4 quarters x 64 channels. Warp = 4 rows x 8 float4 = 128B/row.
    int px4 = tid & 63;            // 0..63
    int cq  = tid >> 6;            // 0..3
    int rr  = px4 >> 3;            // tile row 0..7
    int cc4 = px4 & 7;             // float4 col 0..7

    float4 g = *reinterpret_cast<const float4*>(&sgate[rr][cc4 * 4]);

    const size_t plane4 = HWn / 4;
    int prow4 = ((h0 + rr) * Wn + w0 + cc4 * 4) >> 2;
    const float4* xin = reinterpret_cast<const float4*>(x) +
                        (size_t)b * Cn * plane4 + (size_t)cq * 64 * plane4 + prow4;
    float4* xout = reinterpret_cast<float4*>(out) +
                   (size_t)b * Cn * plane4 + (size_t)cq * 64 * plane4 + prow4;

#pragma unroll 8
    for (int c = 0; c < 64; c++) {
        float4 v = __ldcs(xin + (size_t)c * plane4);
        v.x *= g.x; v.y *= g.y; v.z *= g.z; v.w *= g.w;
        __stcs(xout + (size_t)c * plane4, v);
    }
}

extern "C" void kernel_launch(void* const* d_in, const int* in_sizes, int n_in,
                              void* d_out, int out_size) {
    const float* x  = (const float*)d_in[0];
    const float* cw = (const float*)d_in[1];
    const float* cb = (const float*)d_in[2];
    float* out = (float*)d_out;

    // 512 blocks x 288 threads (1 producer warp + 256 consumers)
    reduce_kernel<<<(Bn * PLANE4) / RPX, 288>>>(x);

    // grid (4, 16, 16) = 1024 blocks x 256 threads
    gate_mul_kernel<<<dim3(Wn / TW, Hn / TH, Bn), 256>>>(x, cw, cb, out);
}